// round 8
// baseline (speedup 1.0000x reference)
#include <cuda_runtime.h>

// LogSig_var: depth-2 log-signature over 64 segments.
// inp: (B, T, 12) fp32, length: (B,) int32 -> out: (B, 64, 78) fp32
// out channels: [0:12) increments, [12:78) Levy areas A_ij (i<j row-major).

#define D_CH 12
#define NSEG 64
#define NPAIR 66
#define TPB 256

// triu_indices(12, k=1) row-major, as constexpr functions (compile-time under
// full unrolling; no device arrays needed).
__host__ __device__ constexpr int pairI(int p) {
    int i = 0, rem = p;
    while (rem >= 11 - i) { rem -= 11 - i; i++; }
    return i;
}
__host__ __device__ constexpr int pairJ(int p) {
    int i = 0, rem = p;
    while (rem >= 11 - i) { rem -= 11 - i; i++; }
    return i + 1 + rem;
}

// SMEM row layout: 12 floats per row + MONOTONE 16B skew every 32 rows.
// Monotone (no &7 wrap) => srow gaps always >= 12 floats, no row overlap.
// Bank property: rows 32 apart start (32*12+4) mod 32 = 4 banks apart, so the
// 8 distinct rows a warp touches hit banks {0,4,...,28} -> conflict-free.
__device__ __forceinline__ int srow(int row) {
    return row * 12 + (row >> 5) * 4;
}

__device__ __forceinline__ void loadRow(const float* sX, int row, float* v) {
    int base = srow(row);
    float4 a = *(const float4*)(sX + base);
    float4 b = *(const float4*)(sX + base + 4);
    float4 c = *(const float4*)(sX + base + 8);
    v[0]=a.x; v[1]=a.y; v[2]=a.z;  v[3]=a.w;
    v[4]=b.x; v[5]=b.y; v[6]=b.z;  v[7]=b.w;
    v[8]=c.x; v[9]=c.y; v[10]=c.z; v[11]=c.w;
}

template<int P0, int P1>
__device__ __forceinline__ void accumCross(const float* cur, const float* nxt, float* acc) {
#pragma unroll
    for (int p = P0; p < P1; p++)
        acc[p - P0] += cur[pairI(p)] * nxt[pairJ(p)] - cur[pairJ(p)] * nxt[pairI(p)];
}

template<int P0, int P1>
__device__ __forceinline__ void writeOut(float* ob, const float* xa, const float* xb,
                                         const float* acc, bool writeInc) {
    if (writeInc) {
#pragma unroll
        for (int c = 0; c < D_CH; c++) ob[c] = xb[c] - xa[c];
    }
#pragma unroll
    for (int p = P0; p < P1; p++) {
        float cross = xa[pairI(p)] * xb[pairJ(p)] - xa[pairJ(p)] * xb[pairI(p)];
        ob[D_CH + p] = 0.5f * (acc[p - P0] - cross);
    }
}

template<bool EXPAND, int P0, int P1>
__device__ __forceinline__ void segment_work(const float* sX, int a, int b, int k,
                                             float* ob, bool writeInc) {
    float x[D_CH], y[D_CH], xa[D_CH];
    float acc[P1 - P0];
#pragma unroll
    for (int q = 0; q < P1 - P0; q++) acc[q] = 0.0f;

    int r0 = EXPAND ? (a / k) : a;
    loadRow(sX, r0, x);
#pragma unroll
    for (int c = 0; c < D_CH; c++) xa[c] = x[c];

    int t = a;
    for (;;) {
        int r1 = EXPAND ? ((t + 1) / k) : (t + 1);
        loadRow(sX, r1, y);
        accumCross<P0, P1>(x, y, acc);
        t++;
        if (t >= b) { writeOut<P0, P1>(ob, xa, y, acc, writeInc); return; }

        int r2 = EXPAND ? ((t + 1) / k) : (t + 1);
        loadRow(sX, r2, x);
        accumCross<P0, P1>(y, x, acc);
        t++;
        if (t >= b) { writeOut<P0, P1>(ob, xa, x, acc, writeInc); return; }
    }
}

__global__ __launch_bounds__(TPB, 2)
void logsig_kernel(const float* __restrict__ inp, const int* __restrict__ length,
                   float* __restrict__ out, int T) {
    extern __shared__ float sX[];
    const int blk = blockIdx.x;
    const int L = length[blk];

    // Stage X[0..L) into SMEM (coalesced float4 reads; rows are 48B = 3xfloat4)
    const float4* Xg = (const float4*)(inp + (size_t)blk * T * D_CH);
    const int n4 = L * 3;
    for (int i = threadIdx.x; i < n4; i += TPB) {
        float4 v = Xg[i];
        int row = i / 3;
        int q = i - row * 3;
        *(float4*)&sX[row * 12 + (row >> 5) * 4 + q * 4] = v;
    }
    __syncthreads();

    const bool expand = (L < NSEG + 1);
    const int k    = expand ? (NSEG / L + 1) : 1;
    const int Leff = expand ? (k * L) : L;
    const float Lm1 = (float)(Leff - 1);

    const int s = threadIdx.x >> 2;
    const int g = threadIdx.x & 3;

    // tv_j = round(1 + j*(Leff-1)/64); all fp32 intermediates exact (< 2^24),
    // rintf = round-half-to-even matches jnp.round bit-exactly.
    const int a  = (int)rintf(1.0f + ((float)s       * Lm1) * (1.0f / 64.0f)) - 1;
    const int bb = (int)rintf(1.0f + ((float)(s + 1) * Lm1) * (1.0f / 64.0f)) - 1;

    float* ob = out + ((size_t)blk * NSEG + s) * 78;

    if (!expand) {
        switch (g) {
            case 0:  segment_work<false,  0, 17>(sX, a, bb, 1, ob, true);  break;
            case 1:  segment_work<false, 17, 34>(sX, a, bb, 1, ob, false); break;
            case 2:  segment_work<false, 34, 50>(sX, a, bb, 1, ob, false); break;
            default: segment_work<false, 50, 66>(sX, a, bb, 1, ob, false); break;
        }
    } else {
        switch (g) {
            case 0:  segment_work<true,  0, 17>(sX, a, bb, k, ob, true);  break;
            case 1:  segment_work<true, 17, 34>(sX, a, bb, k, ob, false); break;
            case 2:  segment_work<true, 34, 50>(sX, a, bb, k, ob, false); break;
            default: segment_work<true, 50, 66>(sX, a, bb, k, ob, false); break;
        }
    }
}

extern "C" void kernel_launch(void* const* d_in, const int* in_sizes, int n_in,
                              void* d_out, int out_size) {
    const float* inp    = (const float*)d_in[0];
    const int*   length = (const int*)d_in[1];
    float*       out    = (float*)d_out;

    const int B = in_sizes[1];
    const int T = in_sizes[0] / (B * D_CH);

    // SMEM: T rows * 12 floats + monotone skew ((T>>5)*4) + slack
    const size_t smemBytes = (size_t)(T * 12 + (T >> 5) * 4 + 16) * sizeof(float);

    cudaFuncSetAttribute(logsig_kernel,
                         cudaFuncAttributeMaxDynamicSharedMemorySize,
                         (int)smemBytes);

    logsig_kernel<<<B, TPB, smemBytes>>>(inp, length, out, T);
}

// round 9
// speedup vs baseline: 22.1289x; 22.1289x over previous
#include <cuda_runtime.h>

// LogSig_var: depth-2 log-signature over 64 segments.
// inp: (B, T, 12) fp32, length: (B,) int32 -> out: (B, 64, 78) fp32
// out channels: [0:12) increments, [12:78) Levy areas A_ij (i<j row-major).
//
// Block per batch; X[0..L) staged in SMEM (monotone 16B skew per 32 rows).
// Thread = (segment s = tid>>2, pair-group g = tid&3). All pair indices are
// template parameters -> guaranteed compile-time -> all arrays in registers.

#define D_CH 12
#define NSEG 64
#define TPB 256

__host__ __device__ constexpr int pairI(int p) {
    int i = 0, rem = p;
    while (rem >= 11 - i) { rem -= 11 - i; i++; }
    return i;
}
__host__ __device__ constexpr int pairJ(int p) {
    int i = 0, rem = p;
    while (rem >= 11 - i) { rem -= 11 - i; i++; }
    return i + 1 + rem;
}

__device__ __forceinline__ int srow(int row) {
    return row * 12 + (row >> 5) * 4;   // monotone skew: no overlap, 4-bank stride / 32 rows
}

struct Row { float v[D_CH]; };

__device__ __forceinline__ void loadRow(const float* sX, int row, Row& r) {
    int base = srow(row);
    float4 a = *(const float4*)(sX + base);
    float4 b = *(const float4*)(sX + base + 4);
    float4 c = *(const float4*)(sX + base + 8);
    r.v[0]=a.x; r.v[1]=a.y; r.v[2]=a.z;  r.v[3]=a.w;
    r.v[4]=b.x; r.v[5]=b.y; r.v[6]=b.z;  r.v[7]=b.w;
    r.v[8]=c.x; r.v[9]=c.y; r.v[10]=c.z; r.v[11]=c.w;
}

// Template recursion: P is a non-type template param, so pairI(P)/pairJ(P)
// are constexpr-forced and every subscript below is a literal constant.
template<int P, int PEND>
struct Pairs {
    static __device__ __forceinline__ void acc(const Row& cur, const Row& nxt, float* a) {
        constexpr int i = pairI(P);
        constexpr int j = pairJ(P);
        float t = a[0];
        t = fmaf(cur.v[i],  nxt.v[j], t);
        t = fmaf(-cur.v[j], nxt.v[i], t);
        a[0] = t;
        Pairs<P + 1, PEND>::acc(cur, nxt, a + 1);
    }
    static __device__ __forceinline__ void out(float* ob, const Row& xa, const Row& xb,
                                               const float* a) {
        constexpr int i = pairI(P);
        constexpr int j = pairJ(P);
        float cross = xa.v[i] * xb.v[j] - xa.v[j] * xb.v[i];
        ob[D_CH + P] = 0.5f * (a[0] - cross);
        Pairs<P + 1, PEND>::out(ob, xa, xb, a + 1);
    }
};
template<int P>
struct Pairs<P, P> {
    static __device__ __forceinline__ void acc(const Row&, const Row&, float*) {}
    static __device__ __forceinline__ void out(float*, const Row&, const Row&, const float*) {}
};

template<int P0, int P1>
__device__ __forceinline__ void writeOut(float* ob, const Row& xa, const Row& xb,
                                         const float* acc, bool writeInc) {
    if (writeInc) {
#pragma unroll
        for (int c = 0; c < D_CH; c++) ob[c] = xb.v[c] - xa.v[c];
    }
    Pairs<P0, P1>::out(ob, xa, xb, acc);
}

template<bool EXPAND, int P0, int P1>
__device__ __forceinline__ void segment_work(const float* sX, int a, int b, int k,
                                             float* ob, bool writeInc) {
    Row x, y, xa;
    float acc[P1 - P0];
#pragma unroll
    for (int q = 0; q < P1 - P0; q++) acc[q] = 0.0f;

    loadRow(sX, EXPAND ? (a / k) : a, x);
    xa = x;

    int t = a;
    for (;;) {
        loadRow(sX, EXPAND ? ((t + 1) / k) : (t + 1), y);
        Pairs<P0, P1>::acc(x, y, acc);
        t++;
        if (t >= b) { writeOut<P0, P1>(ob, xa, y, acc, writeInc); return; }

        loadRow(sX, EXPAND ? ((t + 1) / k) : (t + 1), x);
        Pairs<P0, P1>::acc(y, x, acc);
        t++;
        if (t >= b) { writeOut<P0, P1>(ob, xa, x, acc, writeInc); return; }
    }
}

__global__ __launch_bounds__(TPB, 2)
void logsig_kernel(const float* __restrict__ inp, const int* __restrict__ length,
                   float* __restrict__ out, int T) {
    extern __shared__ float sX[];
    const int blk = blockIdx.x;
    const int L = length[blk];

    // Stage X[0..L) into SMEM (coalesced float4 reads; rows are 48B = 3xfloat4)
    const float4* Xg = (const float4*)(inp + (size_t)blk * T * D_CH);
    const int n4 = L * 3;
    for (int i = threadIdx.x; i < n4; i += TPB) {
        float4 v = Xg[i];
        int row = i / 3;
        int q = i - row * 3;
        *(float4*)&sX[row * 12 + (row >> 5) * 4 + q * 4] = v;
    }
    __syncthreads();

    const bool expand = (L < NSEG + 1);
    const int k    = expand ? (NSEG / L + 1) : 1;
    const int Leff = expand ? (k * L) : L;
    const float Lm1 = (float)(Leff - 1);

    const int s = threadIdx.x >> 2;
    const int g = threadIdx.x & 3;

    // tv_j = round(1 + j*(Leff-1)/64); all fp32 intermediates exact (< 2^24),
    // rintf = round-half-to-even matches jnp.round bit-exactly.
    const int a  = (int)rintf(1.0f + ((float)s       * Lm1) * (1.0f / 64.0f)) - 1;
    const int bb = (int)rintf(1.0f + ((float)(s + 1) * Lm1) * (1.0f / 64.0f)) - 1;

    float* ob = out + ((size_t)blk * NSEG + s) * 78;

    if (!expand) {
        switch (g) {
            case 0:  segment_work<false,  0, 17>(sX, a, bb, 1, ob, true);  break;
            case 1:  segment_work<false, 17, 34>(sX, a, bb, 1, ob, false); break;
            case 2:  segment_work<false, 34, 50>(sX, a, bb, 1, ob, false); break;
            default: segment_work<false, 50, 66>(sX, a, bb, 1, ob, false); break;
        }
    } else {
        switch (g) {
            case 0:  segment_work<true,  0, 17>(sX, a, bb, k, ob, true);  break;
            case 1:  segment_work<true, 17, 34>(sX, a, bb, k, ob, false); break;
            case 2:  segment_work<true, 34, 50>(sX, a, bb, k, ob, false); break;
            default: segment_work<true, 50, 66>(sX, a, bb, k, ob, false); break;
        }
    }
}

extern "C" void kernel_launch(void* const* d_in, const int* in_sizes, int n_in,
                              void* d_out, int out_size) {
    const float* inp    = (const float*)d_in[0];
    const int*   length = (const int*)d_in[1];
    float*       out    = (float*)d_out;

    const int B = in_sizes[1];
    const int T = in_sizes[0] / (B * D_CH);

    // SMEM: T rows * 12 floats + monotone skew ((T>>5)*4) + slack
    const size_t smemBytes = (size_t)(T * 12 + (T >> 5) * 4 + 16) * sizeof(float);

    cudaFuncSetAttribute(logsig_kernel,
                         cudaFuncAttributeMaxDynamicSharedMemorySize,
                         (int)smemBytes);

    logsig_kernel<<<B, TPB, smemBytes>>>(inp, length, out, T);
}